// round 12
// baseline (speedup 1.0000x reference)
#include <cuda_runtime.h>

// Problem constants (fixed by the reference)
#define BB 16
#define SS 2048
#define HH 1024

#define NPROD 128                 // u2 producer blocks; <=148 so all resident even at occ 1
#define BLKS_PER_BATCH (SS / 16)  // 128 score blocks per batch row

// Globals. Invariant: all zero at entry of every kernel_launch call.
// Zero at module load; the final batch-tail block restores them each call.
__device__ float g_u2[HH];
__device__ int   g_done;
__device__ int   g_cnt[BB];
__device__ int   g_batches;

// ---------------------------------------------------------------------------
// One fused kernel, grid 2048 x 512:
//  - blocks 0..127 compute u2 = v^T @ W[:,H:2H] (64 rows x 128 cols each),
//    REDG-atomic into g_u2, fence, bump g_done.
//  - blocks 128..2047 prefetch their 16 enc rows into registers FIRST, then
//    spin on g_done (thread 0, nanosleep poll) -> u2 latency hides under the
//    wave-1 enc prefetch instead of stalling the chip.
//  - all blocks stage u2 to smem (__ldcg, L2-coherent), dot 16 rows, write
//    scores (__stcg).
//  - last block to finish per batch (atomic counter) runs that batch's
//    softmax from L2-hot scores. 16th batch-tail resets globals.
// ---------------------------------------------------------------------------
__global__ __launch_bounds__(512) void fused_kernel(
    const float* __restrict__ attn_w,  // [H, 2H] row-major
    const float* __restrict__ v,       // [1, H]
    const float* __restrict__ enc,     // [B, S, H]
    float* __restrict__ out)           // [B*S] scores -> softmax probs
{
    const int tid  = threadIdx.x;
    const int warp = tid >> 5;          // 0..15
    const int lane = tid & 31;
    const int bid  = blockIdx.x;

    __shared__ float4 su2[HH / 4];      // 4 KB
    __shared__ float4 part[16][32];     // 2 KB (producer reduce)
    __shared__ float  red[16];
    __shared__ int    s_last, s_final;

    const int row = bid * 16 + warp;    // 0 .. B*S-1
    const float4* e = reinterpret_cast<const float4*>(enc) + (size_t)row * (HH / 4);
    float4 ev[8];

    if (bid < NPROD) {
        // ---- u2 producer: 128-col tile x 64-row chunk ----
        const int j0 = (bid & 7) * 128;       // 8 column tiles (32 x float4)
        const int h0 = (bid >> 3) * 64;       // 16 chunks of 64 rows
        const float4* base = reinterpret_cast<const float4*>(attn_w + HH + j0) + lane;
        const size_t rs = (2 * HH) / 4;

        float4 acc = make_float4(0.f, 0.f, 0.f, 0.f);
#pragma unroll
        for (int i = 0; i < 4; ++i) {
            const int h = h0 + warp + i * 16;
            const float vv = __ldg(v + h);
            const float4 w4 = __ldg(base + (size_t)h * rs);
            acc.x += vv * w4.x; acc.y += vv * w4.y;
            acc.z += vv * w4.z; acc.w += vv * w4.w;
        }
        part[warp][lane] = acc;
        __syncthreads();
        if (warp == 0) {
            float4 s = part[0][lane];
#pragma unroll
            for (int w = 1; w < 16; ++w) {
                const float4 p = part[w][lane];
                s.x += p.x; s.y += p.y; s.z += p.z; s.w += p.w;
            }
            float* dst = g_u2 + j0 + lane * 4;
            atomicAdd(dst + 0, s.x);
            atomicAdd(dst + 1, s.y);
            atomicAdd(dst + 2, s.z);
            atomicAdd(dst + 3, s.w);
        }
        __syncthreads();
        if (tid == 0) { __threadfence(); atomicAdd(&g_done, 1); }
    } else {
        // ---- consumer: prefetch enc into registers BEFORE the spin ----
#pragma unroll
        for (int it = 0; it < 8; ++it)
            ev[it] = __ldcs(e + it * 32 + lane);
    }

    // ---- wait for u2 complete ----
    if (tid == 0) {
        while (*((volatile int*)&g_done) != NPROD)
            __nanosleep(64);
    }
    __syncthreads();
    __threadfence();   // acquire

    // ---- stage u2 (L2-coherent) ----
    if (tid < HH / 4)
        su2[tid] = __ldcg(reinterpret_cast<const float4*>(g_u2) + tid);
    __syncthreads();

    if (bid < NPROD) {   // producers load their enc rows now
#pragma unroll
        for (int it = 0; it < 8; ++it)
            ev[it] = __ldcs(e + it * 32 + lane);
    }

    // ---- dot product: score = enc[row] . u2 ----
    float acc = 0.f;
#pragma unroll
    for (int it = 0; it < 8; ++it) {
        const float4 uv = su2[it * 32 + lane];
        acc += ev[it].x * uv.x + ev[it].y * uv.y + ev[it].z * uv.z + ev[it].w * uv.w;
    }
#pragma unroll
    for (int m = 16; m; m >>= 1)
        acc += __shfl_xor_sync(0xffffffffu, acc, m);
    if (lane == 0) __stcg(out + row, acc);

    // ---- tail: last block of this batch does the batch softmax ----
    const int batch = bid >> 7;   // 128 blocks per batch
    __threadfence();              // release scores (all threads)
    __syncthreads();
    if (tid == 0)
        s_last = (atomicAdd(&g_cnt[batch], 1) == BLKS_PER_BATCH - 1);
    __syncthreads();
    if (!s_last) return;

    // softmax over this batch's 2048 scores (512 threads x float4), L2-hot
    float4* po = reinterpret_cast<float4*>(out + (size_t)batch * SS);
    float4 x = __ldcg(po + tid);

    float mx = fmaxf(fmaxf(x.x, x.y), fmaxf(x.z, x.w));
#pragma unroll
    for (int m = 16; m; m >>= 1)
        mx = fmaxf(mx, __shfl_xor_sync(0xffffffffu, mx, m));
    if (lane == 0) red[warp] = mx;
    __syncthreads();
    float bmax = red[0];
#pragma unroll
    for (int w = 1; w < 16; ++w) bmax = fmaxf(bmax, red[w]);
    __syncthreads();

    x.x = __expf(x.x - bmax); x.y = __expf(x.y - bmax);
    x.z = __expf(x.z - bmax); x.w = __expf(x.w - bmax);
    float s = x.x + x.y + x.z + x.w;
#pragma unroll
    for (int m = 16; m; m >>= 1)
        s += __shfl_xor_sync(0xffffffffu, s, m);
    if (lane == 0) red[warp] = s;
    __syncthreads();
    float tot = 0.f;
#pragma unroll
    for (int w = 0; w < 16; ++w) tot += red[w];
    const float inv = 1.0f / tot;
    x.x *= inv; x.y *= inv; x.z *= inv; x.w *= inv;
    po[tid] = x;

    // ---- cleanup: the 16th (final) batch-tail restores the globals ----
    __syncthreads();
    if (tid == 0)
        s_final = (atomicAdd(&g_batches, 1) == BB - 1);
    __syncthreads();
    if (s_final) {
        if (tid < HH / 4)
            reinterpret_cast<float4*>(g_u2)[tid] = make_float4(0.f, 0.f, 0.f, 0.f);
        if (tid < BB) g_cnt[tid] = 0;
        if (tid == 0) { g_done = 0; g_batches = 0; }
    }
}

// ---------------------------------------------------------------------------
// Inputs (metadata order): hidden [B,1,H], encoder_outputs [B,S,H],
//                          attn_w [H,2H], attn_b [H], v [1,H]
// hidden and attn_b are provably unused (softmax shift invariance folds them
// into a per-row constant).
// Output: [B,1,S] float32.
// ---------------------------------------------------------------------------
extern "C" void kernel_launch(void* const* d_in, const int* in_sizes, int n_in,
                              void* d_out, int out_size)
{
    const float* enc    = (const float*)d_in[1];
    const float* attn_w = (const float*)d_in[2];
    const float* v      = (const float*)d_in[4];
    float* out = (float*)d_out;

    fused_kernel<<<(BB * SS) / 16, 512>>>(attn_w, v, enc, out);
}